// round 1
// baseline (speedup 1.0000x reference)
#include <cuda_runtime.h>

// FNN knowledge-tracing scan. Fixed shapes from the dataset:
//   B=128, T=50, K=100, M=8, C=32, R=M*C=256
// Key algebraic reductions vs the reference:
//   - memory update touches only row sk_t  -> compute the GEMV for that row only
//   - g_t / g_t1 outputs are raw score copies (one-hot mask sums to 1)
//   - p_t uses norm . W_pred = (sum cog*w) / (sum cog)  (normalize fused into reduction)
// One block per batch element; the T=50 scan runs inside the kernel
// (sequential dependence through mem), state lives in shared memory.

#define Bc 128
#define Kc 100
#define Mc 8
#define Cc 32
#define Rc 256   // Mc*Cc

__global__ __launch_bounds__(128, 1)
void fnn_scan_kernel(const float* __restrict__ scores,   // [B, T+1]
                     const int*   __restrict__ skills,   // [B, T+1]
                     const float* __restrict__ mean,     // [M]
                     const float* __restrict__ sigma,    // [M]
                     const float* __restrict__ Wcog,     // [C, R] row-major
                     const float* __restrict__ Wpred,    // [C]
                     const float* __restrict__ bpred,    // [1]
                     const float* __restrict__ cog0,     // [K, C]
                     float* __restrict__ out,            // 4 x [B, T] concatenated
                     int T)
{
    __shared__ float mem_s[Kc * Cc];        // 12800 B  cognition memory for this b
    __shared__ float rule_s[Rc];            // fuzzy rule vector for active row
    __shared__ float red_s[4][Cc];          // partial sums across p
    __shared__ float sc_s[64];              // per-b score sequence (T+1 <= 64)
    __shared__ int   sk_s[64];              // per-b skill sequence
    __shared__ float mean_s[Mc];
    __shared__ float sinv_s[Mc];            // 1/sigma^2
    __shared__ float wp_s[Cc];

    const int b   = blockIdx.x;
    const int tid = threadIdx.x;
    const int c   = tid & 31;
    const int p   = tid >> 5;

    // --- one-time loads -----------------------------------------------------
    // W_cog column slice held in registers: w[q] = Wcog[c][p*64 + q]
    float w[64];
#pragma unroll
    for (int q = 0; q < 64; q++)
        w[q] = Wcog[c * Rc + p * 64 + q];

    for (int i = tid; i < Kc * Cc; i += 128)
        mem_s[i] = cog0[i];

    for (int i = tid; i <= T; i += 128) {
        sc_s[i] = scores[b * (T + 1) + i];
        sk_s[i] = skills[b * (T + 1) + i];
    }
    if (tid < Mc) {
        mean_s[tid] = mean[tid];
        float s = sigma[tid];
        sinv_s[tid] = 1.0f / (s * s);
    }
    if (tid < Cc) wp_s[tid] = Wpred[tid];
    const float bp = bpred[0];
    const int BT = Bc * T;
    __syncthreads();

    // --- sequential scan over time -----------------------------------------
    for (int t = 0; t < T; t++) {
        const int   sk  = sk_s[t];
        const int   sk1 = sk_s[t + 1];
        const float sc  = sc_s[t];
        const float sc1 = sc_s[t + 1];

        // build rule[r] = exp(-(sc-mean[i])^2 / sigma[i]^2) * mem[sk][j],
        // r = i*32 + j; each thread fills 2 entries.
#pragma unroll
        for (int u = 0; u < 2; u++) {
            int   r  = tid + u * 128;
            int   i  = r >> 5;
            int   j  = r & 31;
            float d  = sc - mean_s[i];
            float fs = __expf(-d * d * sinv_s[i]);
            rule_s[r] = fs * mem_s[sk * Cc + j];
        }
        __syncthreads();

        // GEMV slice: acc = sum_{q} rule[p*64+q] * Wcog[c][p*64+q]
        float acc = 0.0f;
        const float4* r4 = reinterpret_cast<const float4*>(&rule_s[p * 64]);
#pragma unroll
        for (int q = 0; q < 16; q++) {
            float4 rv = r4[q];
            acc = fmaf(rv.x, w[4 * q + 0], acc);
            acc = fmaf(rv.y, w[4 * q + 1], acc);
            acc = fmaf(rv.z, w[4 * q + 2], acc);
            acc = fmaf(rv.w, w[4 * q + 3], acc);
        }
        red_s[p][c] = acc;
        __syncthreads();

        if (p == 0) {
            float tot = red_s[0][c] + red_s[1][c] + red_s[2][c] + red_s[3][c];
            float cog = 1.0f / (1.0f + __expf(-tot));
            float s1  = cog;              // sum of cog      (for normalization)
            float s2  = cog * wp_s[c];    // sum of cog*Wp   (for p_t)
#pragma unroll
            for (int off = 16; off; off >>= 1) {
                s1 += __shfl_xor_sync(0xffffffffu, s1, off);
                s2 += __shfl_xor_sync(0xffffffffu, s2, off);
            }
            float norm = cog / s1;
            mem_s[sk * Cc + c] = norm;    // scatter-update the active row
            __syncwarp();

            // p_t1 reads the POST-update memory at row sk1
            float d1 = mem_s[sk1 * Cc + c] * wp_s[c];
#pragma unroll
            for (int off = 16; off; off >>= 1)
                d1 += __shfl_xor_sync(0xffffffffu, d1, off);

            if (c == 0) {
                float pt  = 1.0f / (1.0f + __expf(-(s2 / s1 + bp)));
                float pt1 = 1.0f / (1.0f + __expf(-(d1 + bp)));
                int o = b * T + t;
                out[o]          = pt;   // p_t
                out[BT + o]     = pt1;  // p_t1
                out[2 * BT + o] = sc;   // g_t
                out[3 * BT + o] = sc1;  // g_t1
            }
        }
        __syncthreads();   // mem_s update must be visible before next rule build
    }
}

extern "C" void kernel_launch(void* const* d_in, const int* in_sizes, int n_in,
                              void* d_out, int out_size)
{
    int idx = 0;
    const float* scores = (const float*)d_in[idx++];
    const int*   skills = (const int*)  d_in[idx++];
    if (n_in >= 9) idx++;                       // skip scalar T input if present
    const float* mean   = (const float*)d_in[idx++];
    const float* sigma  = (const float*)d_in[idx++];
    const float* Wcog   = (const float*)d_in[idx++];
    const float* Wpred  = (const float*)d_in[idx++];
    const float* bpred  = (const float*)d_in[idx++];
    const float* cog0   = (const float*)d_in[idx++];

    const int T = in_sizes[0] / Bc - 1;         // scores is [B, T+1]
    float* out = (float*)d_out;

    fnn_scan_kernel<<<Bc, 128>>>(scores, skills, mean, sigma,
                                 Wcog, Wpred, bpred, cog0, out, T);
}

// round 7
// speedup vs baseline: 2.2074x; 2.2074x over previous
#include <cuda_runtime.h>

// FNN knowledge-tracing scan, chain-decomposed. Shapes: B=128, T=50, K=100, M=8, C=32, R=256.
//
// Structure exploited:
//  * step t reads & writes ONLY memory row sk_t  -> the scan splits into
//    independent per-(b, skill) chains (avg length ~1.3).
//  * p_t1[b,t] = p_t[b, qidx[t]] where qidx[t] = last occurrence of sk_{t+1}
//    in sk[0..t]; if none, sigmoid(cog0[sk_{t+1}] . Wp + b).
//  * g_t = sc_t, g_t1 = sc_{t+1}.
//
// Grid (B, 4): block (b, g) owns chains with head-rank ≡ g (mod 4) and runs
// its own event loop — 128 threads (4 warps), ONE __syncthreads per event,
// GEMV partials parity-double-buffered, per-warp state replicas updated
// redundantly (identical arithmetic in all warps keeps replicas in sync).
// Output ownership: plane0[t] by owner of event t; plane1[t] by owner of
// event qidx[t], or g==0 computing the cog0-row prediction when qidx[t]<0;
// planes 2/3 by g==0. Exactly one writer per slot.

#define Bc 128
#define Kc 100
#define Mc 8
#define Cc 32
#define Rc 256
#define TMAX 64
#define MAXH 16   // max chains per block: ceil(T/4) = 13

__global__ __launch_bounds__(128, 4)
void fnn_group_kernel(const float* __restrict__ scores,   // [B, T+1]
                      const int*   __restrict__ skills,   // [B, T+1]
                      const float* __restrict__ mean,     // [M]
                      const float* __restrict__ sigma,    // [M]
                      const float* __restrict__ Wcog,     // [C, R]
                      const float* __restrict__ Wpred,    // [C]
                      const float* __restrict__ bpred,    // [1]
                      const float* __restrict__ cog0,     // [K, C]
                      float* __restrict__ out,            // 4 x [B, T]
                      int T)
{
    __shared__ __align__(16) float state_s[4][Cc];   // per-WARP chain state
    __shared__ __align__(16) float red_s[2][4][Cc];  // GEMV partials (parity DB)
    __shared__ __align__(16) float hrows_s[MAXH][Cc];// prefetched cog0 head rows
    __shared__ float sc_s[TMAX];
    __shared__ int   sk_s[TMAX];
    __shared__ int   prevsame[TMAX];   // last u<t with sk[u]==sk[t]
    __shared__ int   nextsame[TMAX];   // forward link within a chain
    __shared__ int   qidx[TMAX];       // last u<=t with sk[u]==sk[t+1]
    __shared__ int   heads_s[TMAX];    // chain heads in rank order
    __shared__ int   sched_s[TMAX];    // this block's event list
    __shared__ unsigned char own_s[TMAX];
    __shared__ unsigned hm_s[2];
    __shared__ int   hskill_s[MAXH];
    __shared__ int   nev_c, nhs_c;
    __shared__ float pt_s[TMAX];
    __shared__ float mean_s[Mc], sinv_s[Mc], wp_s[Cc];

    const int b   = blockIdx.x;
    const int g   = blockIdx.y;
    const int tid = threadIdx.x;
    const int p   = tid >> 5;          // warp 0..3
    const int c   = tid & 31;          // channel / lane

    // ---- W_cog slice in registers: w[q] = Wcog[c][p*64+q] -------------------
    float w[64];
    {
        const float4* w4 = reinterpret_cast<const float4*>(Wcog + c * Rc + p * 64);
#pragma unroll
        for (int q = 0; q < 16; q++) {
            float4 v = w4[q];
            w[4*q] = v.x; w[4*q+1] = v.y; w[4*q+2] = v.z; w[4*q+3] = v.w;
        }
    }

    // ---- prologue loads -----------------------------------------------------
    if (tid <= T) {
        sc_s[tid] = scores[b * (T + 1) + tid];
        sk_s[tid] = skills[b * (T + 1) + tid];
    }
    if (tid < TMAX) { nextsame[tid] = -1; own_s[tid] = 0; }
    if (tid < Mc) {
        mean_s[tid] = mean[tid];
        float s = sigma[tid];
        sinv_s[tid] = 1.0f / (s * s);
    }
    if (tid >= 32 && tid < 64) wp_s[tid - 32] = Wpred[tid - 32];
    const float bp = bpred[0];
    __syncthreads();

    // ---- occurrence structure ----------------------------------------------
    if (tid < T) {                     // prevsame
        int t = tid, sk = sk_s[t], pv = -1;
        for (int uu = t - 1; uu >= 0; uu--)
            if (sk_s[uu] == sk) { pv = uu; break; }
        prevsame[t] = pv;
    } else if (tid >= 64 && tid - 64 < T) {  // qidx (includes u==t)
        int t = tid - 64, sk1 = sk_s[t + 1], q = -1;
        for (int uu = t; uu >= 0; uu--)
            if (sk_s[uu] == sk1) { q = uu; break; }
        qidx[t] = q;
    }
    __syncthreads();

    if (tid < T && prevsame[tid] >= 0)
        nextsame[prevsame[tid]] = tid;

    bool ishead = (tid < T) && (prevsame[tid] < 0);
    if (tid < 64) {                    // warps 0,1 fully participate
        unsigned m = __ballot_sync(0xffffffffu, ishead);
        if ((tid & 31) == 0) hm_s[tid >> 5] = m;
    }
    __syncthreads();

    const int nheads = __popc(hm_s[0]) + __popc(hm_s[1]);
    if (tid < 64 && ishead) {
        int rank = __popc(hm_s[tid >> 5] & ((1u << (tid & 31)) - 1u))
                 + ((tid >= 32) ? __popc(hm_s[0]) : 0);
        heads_s[rank] = tid;
    }
    __syncthreads();

    // ---- this block's schedule (thread 0 serial walk, ~13 iters) ------------
    if (tid == 0) {
        int n = 0, hs = 0;
        for (int hi = g; hi < nheads; hi += 4) {
            int t = heads_s[hi];
            hskill_s[hs] = sk_s[t];
            int code = 256 | (hs << 9);       // head flag + hslot
            while (t >= 0) {
                sched_s[n++] = t | code;
                own_s[t] = 1;
                code = 0;
                t = nextsame[t];
            }
            hs++;
        }
        nev_c = n; nhs_c = hs;
    }
    __syncthreads();
    const int nev = nev_c;

    // ---- prefetch cog0 rows for my chain heads ------------------------------
    for (int i = p; i < nhs_c; i += 4)
        hrows_s[i][c] = cog0[hskill_s[i] * Cc + c];
    __syncthreads();

    // ---- event loop (block-local, one barrier per event) --------------------
    const float m0 = mean_s[2 * p], m1 = mean_s[2 * p + 1];
    const float v0 = sinv_s[2 * p], v1 = sinv_s[2 * p + 1];
    const float wpc = wp_s[c];
    float* mystate = state_s[p];
    int par = 0;

    for (int e = 0; e < nev; e++) {
        const int code = sched_s[e];
        const int t = code & 255;
        if (code & 256)                // chain head: init per-warp replica
            mystate[c] = hrows_s[code >> 9][c];
        __syncwarp();                  // cross-lane write->read of mystate

        const float sc = sc_s[t];
        float d0 = sc - m0, d1 = sc - m1;
        float f0 = __expf(-d0 * d0 * v0);
        float f1 = __expf(-d1 * d1 * v1);

        // partial = f0 * <state, w[0:32]> + f1 * <state, w[32:64]>
        float a0 = 0, a1 = 0, a2 = 0, a3 = 0;
        float e0 = 0, e1 = 0, e2 = 0, e3 = 0;
        const float4* st4 = reinterpret_cast<const float4*>(mystate);
#pragma unroll
        for (int q = 0; q < 8; q++) {
            float4 s = st4[q];
            a0 = fmaf(s.x, w[4*q],      a0);
            a1 = fmaf(s.y, w[4*q + 1],  a1);
            a2 = fmaf(s.z, w[4*q + 2],  a2);
            a3 = fmaf(s.w, w[4*q + 3],  a3);
            e0 = fmaf(s.x, w[32 + 4*q], e0);
            e1 = fmaf(s.y, w[33 + 4*q], e1);
            e2 = fmaf(s.z, w[34 + 4*q], e2);
            e3 = fmaf(s.w, w[35 + 4*q], e3);
        }
        red_s[par][p][c] = f0 * ((a0 + a1) + (a2 + a3))
                         + f1 * ((e0 + e1) + (e2 + e3));
        __syncthreads();               // the ONLY barrier per event

        // epilogue: redundant in all 4 warps (identical arithmetic keeps
        // the per-warp state replicas bit-identical)
        float tot = red_s[par][0][c] + red_s[par][1][c]
                  + red_s[par][2][c] + red_s[par][3][c];
        float cog = 1.0f / (1.0f + __expf(-tot));
        float s1 = cog, s2 = cog * wpc;      // interleaved butterfly: the two
#pragma unroll                               // chains are independent, SHFL
        for (int off = 16; off; off >>= 1) { // latencies overlap
            s1 += __shfl_xor_sync(0xffffffffu, s1, off);
            s2 += __shfl_xor_sync(0xffffffffu, s2, off);
        }
        float inv = __fdividef(1.0f, s1);
        mystate[c] = cog * inv;              // scatter update (own replica)
        __syncwarp();                        // before next event's reads
        if (tid == 0)
            pt_s[t] = 1.0f / (1.0f + __expf(-(s2 * inv + bp)));
        par ^= 1;
    }
    __syncthreads();

    // ---- tail: each slot has exactly one writer -----------------------------
    const int BT = Bc * T;
    for (int t = tid; t < T; t += 128) {
        int o = b * T + t;
        if (own_s[t]) out[o] = pt_s[t];                 // p_t  (owner of event t)
        int q = qidx[t];
        if (q >= 0) {
            if (own_s[q]) out[BT + o] = pt_s[q];        // p_t1 (owner of event q)
        } else if (g == 0) {                            // p_t1 from initial cog0 row
            const float4* r4 = reinterpret_cast<const float4*>(cog0 + sk_s[t + 1] * Cc);
            float a = 0.0f;
#pragma unroll
            for (int q4 = 0; q4 < 8; q4++) {
                float4 v = r4[q4];
                a = fmaf(v.x, wp_s[4*q4],     a);
                a = fmaf(v.y, wp_s[4*q4 + 1], a);
                a = fmaf(v.z, wp_s[4*q4 + 2], a);
                a = fmaf(v.w, wp_s[4*q4 + 3], a);
            }
            out[BT + o] = 1.0f / (1.0f + __expf(-(a + bp)));
        }
        if (g == 0) {
            out[2 * BT + o] = sc_s[t];                  // g_t
            out[3 * BT + o] = sc_s[t + 1];              // g_t1
        }
    }
}

extern "C" void kernel_launch(void* const* d_in, const int* in_sizes, int n_in,
                              void* d_out, int out_size)
{
    int idx = 0;
    const float* scores = (const float*)d_in[idx++];
    const int*   skills = (const int*)  d_in[idx++];
    if (n_in >= 9) idx++;                       // skip scalar T input if present
    const float* mean   = (const float*)d_in[idx++];
    const float* sigma  = (const float*)d_in[idx++];
    const float* Wcog   = (const float*)d_in[idx++];
    const float* Wpred  = (const float*)d_in[idx++];
    const float* bpred  = (const float*)d_in[idx++];
    const float* cog0   = (const float*)d_in[idx++];

    const int T = in_sizes[0] / Bc - 1;         // scores is [B, T+1]
    float* out = (float*)d_out;

    dim3 grid(Bc, 4);
    fnn_group_kernel<<<grid, 128>>>(scores, skills, mean, sigma,
                                    Wcog, Wpred, bpred, cog0, out, T);
}